// round 3
// baseline (speedup 1.0000x reference)
#include <cuda_runtime.h>
#include <math.h>

// Problem constants
#define HW      262144        // 512*512
#define NTILES  16384         // 2M pixels / 128-pixel tiles
#define GRID1   296           // 2 * 148 SMs
#define K       19
#define KC      1216          // 19*64

// Scratch (no allocation allowed -> __device__ globals)
__device__ float g_psums[GRID1 * KC];
__device__ int   g_pcnts[K * GRID1];     // [class][block] - coalesced for K3 warps
__device__ float g_sums[KC];

// Dynamic smem layout (floats): tile[64*128] | acc[8*1216] | labels(int)[128] | cnt(int)[19] | shift
#define TILE_F   8192
#define ACC_F    (8*1216)
#define SMEM_BYTES ((TILE_F + ACC_F)*4 + 128*4 + 20*4 + 32)

// ---------------------------------------------------------------------------
// K1: streaming centroid scatter-sum.
// Tile = 128 pixels x 64 channels. Per tile:
//   prefetch (4x LDG.128/thread, coalesced) issued during previous tile's
//   accumulate -> STS.128 into XOR-swizzled transpose tile -> accumulate:
//   lanes span channels (label uniform per pixel-quad group), non-atomic RMW
//   into per-group private accumulators (exclusive (g,c) owner).
// Targets dtype (int32 vs int64) detected inline: int64 labels 0..18 have all
// high words zero; false-positive prob for int32 labels ~ 19^-32.
// ---------------------------------------------------------------------------
__global__ __launch_bounds__(512) void k1_kernel(const float* __restrict__ inp,
                                                 const int* __restrict__ tgt32) {
    extern __shared__ float sm[];
    float* tile   = sm;
    float* acc    = sm + TILE_F;
    int*   labels = (int*)(sm + TILE_F + ACC_F);
    int*   cnt    = labels + 128;
    int*   shiftp = cnt + K;
    const int tid = threadIdx.x;

    // zero accumulators + counts; thread 0 detects targets dtype concurrently
    for (int i = tid; i < ACC_F; i += 512) acc[i] = 0.f;
    if (tid < K) cnt[tid] = 0;
    if (tid == 0) {
        int all0 = 1;
        #pragma unroll
        for (int i = 0; i < 32; ++i)
            if (tgt32[2 * i + 1] != 0) all0 = 0;
        shiftp[0] = all0;    // 1 => int64 (stride-2 int32 reads), 0 => int32
    }
    __syncthreads();
    const int shift = shiftp[0];

    // load-phase mapping: q = pixel-quad (0..31), channels w, 16+w, 32+w, 48+w
    const int q = tid & 31, w = tid >> 5;
    const int c0 = w, c1 = 16 + w, c2 = 32 + w, c3 = 48 + w;
    // accumulate-phase mapping: channel ca, pixel-group g (8 groups of 64 thr)
    const int ca = tid & 63, g = tid >> 6, sw = ca & 31;

    int t = blockIdx.x;
    float4 v0, v1, v2, v3;
    int lab = 0;
    {   // prefetch tile t
        const int b = t >> 11, hw0 = (t & 2047) << 7;
        const float* p = inp + ((size_t)b << 24) + hw0 + (q << 2);
        v0 = __ldcs((const float4*)(p + (size_t)c0 * HW));
        v1 = __ldcs((const float4*)(p + (size_t)c1 * HW));
        v2 = __ldcs((const float4*)(p + (size_t)c2 * HW));
        v3 = __ldcs((const float4*)(p + (size_t)c3 * HW));
        if (tid < 128) lab = __ldcs(tgt32 + ((size_t)((b << 18) + hw0 + tid) << shift));
    }

    while (true) {
        __syncthreads();   // previous accumulate done -> tile/labels reusable
        // store phase: XOR-swizzled, conflict-free STS.128
        *(float4*)(tile + c0*128 + ((q ^ (c0 & 31)) << 2)) = v0;
        *(float4*)(tile + c1*128 + ((q ^ (c1 & 31)) << 2)) = v1;
        *(float4*)(tile + c2*128 + ((q ^ (c2 & 31)) << 2)) = v2;
        *(float4*)(tile + c3*128 + ((q ^ (c3 & 31)) << 2)) = v3;
        if (tid < 128) {
            int l = min(max(lab, 0), K - 1);   // crash-proof; mismatch -> rel_err signal
            labels[tid] = l;
            atomicAdd(&cnt[l], 1);
        }
        __syncthreads();

        const int nt = t + GRID1;
        if (nt < NTILES) {   // prefetch next tile: LDG latency hides behind accumulate
            const int b = nt >> 11, hw0 = (nt & 2047) << 7;
            const float* p = inp + ((size_t)b << 24) + hw0 + (q << 2);
            v0 = __ldcs((const float4*)(p + (size_t)c0 * HW));
            v1 = __ldcs((const float4*)(p + (size_t)c1 * HW));
            v2 = __ldcs((const float4*)(p + (size_t)c2 * HW));
            v3 = __ldcs((const float4*)(p + (size_t)c3 * HW));
            if (tid < 128) lab = __ldcs(tgt32 + ((size_t)((b << 18) + hw0 + tid) << shift));
        }

        // accumulate phase: group g handles quads {g, g+8, g+16, g+24};
        // all 64 threads of a group share one pixel-quad -> labels uniform ->
        // thread exclusively owns acc[g][*][ca] -> plain RMW, no atomics.
        {
            const float* trow = tile + ca * 128;
            float* arow = acc + g * 1216 + ca;
            #pragma unroll
            for (int i = 0; i < 4; ++i) {
                const int qq = g + (i << 3);
                float4 x = *(const float4*)(trow + ((qq ^ sw) << 2));
                int4 lb = *(const int4*)(labels + (qq << 2));   // warp broadcast
                arow[lb.x * 64] += x.x;
                arow[lb.y * 64] += x.y;
                arow[lb.z * 64] += x.z;
                arow[lb.w * 64] += x.w;
            }
        }
        if (nt >= NTILES) break;
        t = nt;
    }

    __syncthreads();
    // merge 8 group copies -> per-block partial (deterministic)
    for (int i = tid; i < KC; i += 512) {
        float s = 0.f;
        #pragma unroll
        for (int gg = 0; gg < 8; ++gg) s += acc[gg * 1216 + i];
        g_psums[blockIdx.x * KC + i] = s;
    }
    if (tid < K) g_pcnts[tid * GRID1 + blockIdx.x] = cnt[tid];
}

// ---------------------------------------------------------------------------
// K2: reduce 296 block-partials -> g_sums[1216]. 38 blocks x 256 threads,
// each block owns 32 outputs, 8-way split over partials + shared tree.
// ---------------------------------------------------------------------------
__global__ void k2_kernel() {
    __shared__ float red[256];
    const int tid = threadIdx.x;
    const int o = (blockIdx.x << 5) + (tid & 31);
    const int s = tid >> 5;
    float sum = 0.f;
    const int p0 = s * 37;                 // 296 = 8*37
    #pragma unroll 4
    for (int p = p0; p < p0 + 37; ++p) sum += g_psums[p * KC + o];
    red[tid] = sum;
    __syncthreads();
    if (tid < 128) red[tid] += red[tid + 128];
    __syncthreads();
    if (tid < 64) red[tid] += red[tid + 64];
    __syncthreads();
    if (tid < 32) g_sums[o] = red[tid] + red[tid + 32];
}

// ---------------------------------------------------------------------------
// K3: counts reduce (19 warps, coalesced + shfl) + centroids + loss. 1 block.
// ---------------------------------------------------------------------------
__global__ __launch_bounds__(640) void k3_kernel(float* __restrict__ out) {
    __shared__ float cen[KC];
    __shared__ float nrm[K];
    __shared__ int   cnts[K];
    __shared__ float red[512];
    const int tid = threadIdx.x;
    const int wid = tid >> 5, lane = tid & 31;

    // parallel count reduction: warp per class, coalesced row of 296 ints
    if (wid < K) {
        int s = 0;
        #pragma unroll
        for (int p = lane; p < GRID1; p += 32) s += g_pcnts[wid * GRID1 + p];
        #pragma unroll
        for (int off = 16; off > 0; off >>= 1) s += __shfl_xor_sync(0xffffffffu, s, off);
        if (lane == 0) cnts[wid] = s;
    }
    __syncthreads();
    for (int i = tid; i < KC; i += 640)
        cen[i] = g_sums[i] / fmaxf((float)cnts[i >> 6], 1.0f);
    __syncthreads();
    if (tid < K) {
        float nn = 0.f;
        #pragma unroll
        for (int c = 0; c < 64; ++c) { float v = cen[(tid << 6) + c]; nn += v * v; }
        nrm[tid] = fmaxf(sqrtf(nn), 1e-8f);
    }
    __syncthreads();
    for (int i = tid; i < KC; i += 640)
        cen[i] = cen[i] / nrm[i >> 6];
    __syncthreads();

    float val = 0.f;
    if (tid < K * K) {
        const int k1i = tid / K, k2i = tid % K;
        float dot = 0.f;
        #pragma unroll
        for (int c = 0; c < 64; ++c)
            dot += cen[(k1i << 6) + c] * cen[(k2i << 6) + c];
        val = (k1i == k2i) ? (1.0f - dot) : fmaxf(dot, 0.0f);
    }
    if (tid < 512) red[tid] = val;
    __syncthreads();
    #pragma unroll
    for (int off = 256; off > 0; off >>= 1) {
        if (tid < off) red[tid] += red[tid + off];
        __syncthreads();
    }
    if (tid == 0) out[0] = red[0] / 6859.0f;   // K^3
}

// ---------------------------------------------------------------------------
extern "C" void kernel_launch(void* const* d_in, const int* in_sizes, int n_in,
                              void* d_out, int out_size) {
    // Select pointers by element count (inputs: 134M, targets: 2M) — robust to order.
    int ii = 0, ti = 1;
    if (n_in >= 2 && in_sizes[1] > in_sizes[0]) { ii = 1; ti = 0; }
    const float* inp = (const float*)d_in[ii];
    const int* tgt32 = (const int*)d_in[ti];
    cudaFuncSetAttribute(k1_kernel, cudaFuncAttributeMaxDynamicSharedMemorySize, SMEM_BYTES);
    k1_kernel<<<GRID1, 512, SMEM_BYTES>>>(inp, tgt32);
    k2_kernel<<<38, 256>>>();
    k3_kernel<<<1, 640>>>((float*)d_out);
}

// round 4
// speedup vs baseline: 1.6049x; 1.6049x over previous
#include <cuda_runtime.h>
#include <math.h>

// Problem constants
#define HW      262144        // 512*512
#define NTILES  16384         // 2M pixels / 128-pixel tiles
#define GRID1   296           // 2 * 148 SMs
#define K       19
#define KC      1216          // 19*64

// Scratch (no allocation allowed -> __device__ globals)
__device__ float g_psums[GRID1 * KC];
__device__ int   g_pcnts[K * GRID1];     // [class][block] - coalesced for K3 warps
__device__ float g_sums[KC];

// ---------------------------------------------------------------------------
// K1: streaming centroid scatter-sum, class-owned register accumulation.
//   - warps 0..15 (512 thr): coalesced LDG.128 -> scalar STS into pixel-major
//     swizzled tile (conflict-free both ways).
//   - warp 19: per-tile counting sort of 128 labels (histogram + shfl prefix +
//     scatter), double-buffered, built during the previous accumulate window.
//   - warps 0..18: warp k owns class k; lanes hold 2 register accumulators
//     (channels lane, lane+32); walk bucket k: 1 LDS + 1 FADD per element.
//   No accumulator smem RMW, no count atomics in hot path.
// ---------------------------------------------------------------------------
__global__ __launch_bounds__(640, 2) void k1_kernel(const float* __restrict__ inp,
                                                    const int* __restrict__ tgt32) {
    __shared__ float tile[8192];          // [pixel 0..127][col' 0..63], swizzled
    __shared__ int   order[2][128];
    __shared__ int   bstart[2][19];
    __shared__ int   bcnt[2][19];
    __shared__ int   bcur[2][19];

    const int tid  = threadIdx.x;
    const int lane = tid & 31;
    const int wid  = tid >> 5;
    const int bid  = blockIdx.x;

    // loader mapping (tid < 512): q = pixel-quad, channels w,16+w,32+w,48+w
    const int q = tid & 31, w = (tid >> 5) & 15;
    const int c0 = w, c1 = 16 + w, c2 = 32 + w, c3 = 48 + w;
    // swizzled column slots for this loader (row group q fixed)
    const int s0 = c0 ^ q, s1 = c1 ^ q, s2 = 32 | (c0 ^ q), s3 = 32 | (c1 ^ q);

    float a0 = 0.f, a1 = 0.f;
    int   ccnt = 0;
    float4 v0, v1, v2, v3;
    int   lab0 = 0, lab1 = 0, lab2 = 0, lab3 = 0;
    int   shift = 0;

    int t = bid, par = 0;

    // ---- prologue ----
    {
        const int b = t >> 11, hw0 = (t & 2047) << 7;
        if (tid < 512) {
            const float* p = inp + ((size_t)b << 24) + hw0 + (q << 2);
            v0 = __ldcs((const float4*)(p + (size_t)c0 * HW));
            v1 = __ldcs((const float4*)(p + (size_t)c1 * HW));
            v2 = __ldcs((const float4*)(p + (size_t)c2 * HW));
            v3 = __ldcs((const float4*)(p + (size_t)c3 * HW));
        }
        if (wid == 19) {
            // dtype detect: int64 labels 0..18 have all-zero high words
            if (lane == 0) {
                int all0 = 1;
                #pragma unroll
                for (int i = 0; i < 32; ++i)
                    if (tgt32[2 * i + 1] != 0) all0 = 0;
                shift = all0;
            }
            shift = __shfl_sync(0xffffffffu, shift, 0);
            const int tb = (b << 18) + hw0;
            lab0 = tgt32[(size_t)(tb + lane)       << shift];
            lab1 = tgt32[(size_t)(tb + lane +  32) << shift];
            lab2 = tgt32[(size_t)(tb + lane +  64) << shift];
            lab3 = tgt32[(size_t)(tb + lane +  96) << shift];
            // build buckets for tile t into buffer 0
            {
                int l0 = min(max(lab0, 0), 18), l1 = min(max(lab1, 0), 18);
                int l2 = min(max(lab2, 0), 18), l3 = min(max(lab3, 0), 18);
                if (lane < 19) bcnt[0][lane] = 0;
                __syncwarp();
                atomicAdd(&bcnt[0][l0], 1); atomicAdd(&bcnt[0][l1], 1);
                atomicAdd(&bcnt[0][l2], 1); atomicAdd(&bcnt[0][l3], 1);
                __syncwarp();
                int c = (lane < 19) ? bcnt[0][lane] : 0;
                int x = c;
                #pragma unroll
                for (int off = 1; off < 32; off <<= 1) {
                    int y = __shfl_up_sync(0xffffffffu, x, off);
                    if (lane >= off) x += y;
                }
                if (lane < 19) { bstart[0][lane] = x - c; bcur[0][lane] = x - c; }
                __syncwarp();
                int p0 = atomicAdd(&bcur[0][l0], 1); order[0][p0] = lane;
                int p1 = atomicAdd(&bcur[0][l1], 1); order[0][p1] = lane + 32;
                int p2 = atomicAdd(&bcur[0][l2], 1); order[0][p2] = lane + 64;
                int p3 = atomicAdd(&bcur[0][l3], 1); order[0][p3] = lane + 96;
            }
            // prefetch labels for t+GRID1
            const int nt = t + GRID1;
            if (nt < NTILES) {
                const int nb = nt >> 11, nh = (nt & 2047) << 7;
                const int tb2 = (nb << 18) + nh;
                lab0 = tgt32[(size_t)(tb2 + lane)       << shift];
                lab1 = tgt32[(size_t)(tb2 + lane +  32) << shift];
                lab2 = tgt32[(size_t)(tb2 + lane +  64) << shift];
                lab3 = tgt32[(size_t)(tb2 + lane +  96) << shift];
            }
        }
    }

    // ---- main loop ----
    while (true) {
        __syncthreads();   // previous accumulate done: tile + buf[par] reusable targets
        if (tid < 512) {   // store phase: conflict-free scalar STS, pixel-major swizzled
            float* r = tile + (q << 8);          // pixel 4q row base (stride 64)
            r[s0]        = v0.x; r[64 + s0]  = v0.y; r[128 + s0] = v0.z; r[192 + s0] = v0.w;
            r[s1]        = v1.x; r[64 + s1]  = v1.y; r[128 + s1] = v1.z; r[192 + s1] = v1.w;
            r[s2]        = v2.x; r[64 + s2]  = v2.y; r[128 + s2] = v2.z; r[192 + s2] = v2.w;
            r[s3]        = v3.x; r[64 + s3]  = v3.y; r[128 + s3] = v3.z; r[192 + s3] = v3.w;
        }
        __syncthreads();

        const int nt = t + GRID1;
        if (nt < NTILES) {
            if (tid < 512) {   // prefetch next tile's data
                const int nb = nt >> 11, nh = (nt & 2047) << 7;
                const float* p = inp + ((size_t)nb << 24) + nh + (q << 2);
                v0 = __ldcs((const float4*)(p + (size_t)c0 * HW));
                v1 = __ldcs((const float4*)(p + (size_t)c1 * HW));
                v2 = __ldcs((const float4*)(p + (size_t)c2 * HW));
                v3 = __ldcs((const float4*)(p + (size_t)c3 * HW));
            }
            if (wid == 19) {   // build buckets for nt into buf[par^1]; prefetch labels nt+G
                const int pb = par ^ 1;
                int l0 = min(max(lab0, 0), 18), l1 = min(max(lab1, 0), 18);
                int l2 = min(max(lab2, 0), 18), l3 = min(max(lab3, 0), 18);
                if (lane < 19) bcnt[pb][lane] = 0;
                __syncwarp();
                atomicAdd(&bcnt[pb][l0], 1); atomicAdd(&bcnt[pb][l1], 1);
                atomicAdd(&bcnt[pb][l2], 1); atomicAdd(&bcnt[pb][l3], 1);
                __syncwarp();
                int c = (lane < 19) ? bcnt[pb][lane] : 0;
                int x = c;
                #pragma unroll
                for (int off = 1; off < 32; off <<= 1) {
                    int y = __shfl_up_sync(0xffffffffu, x, off);
                    if (lane >= off) x += y;
                }
                if (lane < 19) { bstart[pb][lane] = x - c; bcur[pb][lane] = x - c; }
                __syncwarp();
                int p0 = atomicAdd(&bcur[pb][l0], 1); order[pb][p0] = lane;
                int p1 = atomicAdd(&bcur[pb][l1], 1); order[pb][p1] = lane + 32;
                int p2 = atomicAdd(&bcur[pb][l2], 1); order[pb][p2] = lane + 64;
                int p3 = atomicAdd(&bcur[pb][l3], 1); order[pb][p3] = lane + 96;

                const int nt2 = nt + GRID1;
                if (nt2 < NTILES) {
                    const int nb2 = nt2 >> 11, nh2 = (nt2 & 2047) << 7;
                    const int tb2 = (nb2 << 18) + nh2;
                    lab0 = tgt32[(size_t)(tb2 + lane)       << shift];
                    lab1 = tgt32[(size_t)(tb2 + lane +  32) << shift];
                    lab2 = tgt32[(size_t)(tb2 + lane +  64) << shift];
                    lab3 = tgt32[(size_t)(tb2 + lane +  96) << shift];
                }
            }
        }

        // accumulate phase: warp wid owns class wid; register accumulation
        if (wid < K) {
            const int base = bstart[par][wid];
            const int n    = bcnt[par][wid];
            ccnt += n;
            for (int i = 0; i < n; ++i) {
                const int p = order[par][base + i];           // broadcast
                const float* row = tile + (p << 6);
                const int x = lane ^ ((p >> 2) & 31);
                a0 += row[x];
                a1 += row[32 + x];
            }
        }

        if (nt >= NTILES) break;
        t = nt; par ^= 1;
    }

    // ---- write per-block partials (no smem merge needed) ----
    if (wid < K) {
        g_psums[bid * KC + (wid << 6) + lane]      = a0;
        g_psums[bid * KC + (wid << 6) + 32 + lane] = a1;
        if (lane == 0) g_pcnts[wid * GRID1 + bid] = ccnt;
    }
}

// ---------------------------------------------------------------------------
// K2: reduce 296 block-partials -> g_sums[1216]. 38 blocks x 256 threads.
// ---------------------------------------------------------------------------
__global__ void k2_kernel() {
    __shared__ float red[256];
    const int tid = threadIdx.x;
    const int o = (blockIdx.x << 5) + (tid & 31);
    const int s = tid >> 5;
    float sum = 0.f;
    const int p0 = s * 37;                 // 296 = 8*37
    #pragma unroll 4
    for (int p = p0; p < p0 + 37; ++p) sum += g_psums[p * KC + o];
    red[tid] = sum;
    __syncthreads();
    if (tid < 128) red[tid] += red[tid + 128];
    __syncthreads();
    if (tid < 64) red[tid] += red[tid + 64];
    __syncthreads();
    if (tid < 32) g_sums[o] = red[tid] + red[tid + 32];
}

// ---------------------------------------------------------------------------
// K3: counts reduce (19 warps, coalesced + shfl) + centroids + loss. 1 block.
// ---------------------------------------------------------------------------
__global__ __launch_bounds__(640) void k3_kernel(float* __restrict__ out) {
    __shared__ float cen[KC];
    __shared__ float nrm[K];
    __shared__ int   cnts[K];
    __shared__ float red[512];
    const int tid = threadIdx.x;
    const int wid = tid >> 5, lane = tid & 31;

    if (wid < K) {
        int s = 0;
        #pragma unroll
        for (int p = lane; p < GRID1; p += 32) s += g_pcnts[wid * GRID1 + p];
        #pragma unroll
        for (int off = 16; off > 0; off >>= 1) s += __shfl_xor_sync(0xffffffffu, s, off);
        if (lane == 0) cnts[wid] = s;
    }
    __syncthreads();
    for (int i = tid; i < KC; i += 640)
        cen[i] = g_sums[i] / fmaxf((float)cnts[i >> 6], 1.0f);
    __syncthreads();
    if (tid < K) {
        float nn = 0.f;
        #pragma unroll
        for (int c = 0; c < 64; ++c) { float v = cen[(tid << 6) + c]; nn += v * v; }
        nrm[tid] = fmaxf(sqrtf(nn), 1e-8f);
    }
    __syncthreads();
    for (int i = tid; i < KC; i += 640)
        cen[i] = cen[i] / nrm[i >> 6];
    __syncthreads();

    float val = 0.f;
    if (tid < K * K) {
        const int k1i = tid / K, k2i = tid % K;
        float dot = 0.f;
        #pragma unroll
        for (int c = 0; c < 64; ++c)
            dot += cen[(k1i << 6) + c] * cen[(k2i << 6) + c];
        val = (k1i == k2i) ? (1.0f - dot) : fmaxf(dot, 0.0f);
    }
    if (tid < 512) red[tid] = val;
    __syncthreads();
    #pragma unroll
    for (int off = 256; off > 0; off >>= 1) {
        if (tid < off) red[tid] += red[tid + off];
        __syncthreads();
    }
    if (tid == 0) out[0] = red[0] / 6859.0f;   // K^3
}

// ---------------------------------------------------------------------------
extern "C" void kernel_launch(void* const* d_in, const int* in_sizes, int n_in,
                              void* d_out, int out_size) {
    // Select pointers by element count (inputs: 134M, targets: 2M) — robust to order.
    int ii = 0, ti = 1;
    if (n_in >= 2 && in_sizes[1] > in_sizes[0]) { ii = 1; ti = 0; }
    const float* inp = (const float*)d_in[ii];
    const int* tgt32 = (const int*)d_in[ti];
    k1_kernel<<<GRID1, 640>>>(inp, tgt32);
    k2_kernel<<<38, 256>>>();
    k3_kernel<<<1, 640>>>((float*)d_out);
}

// round 5
// speedup vs baseline: 1.6292x; 1.0152x over previous
#include <cuda_runtime.h>
#include <math.h>

// Problem constants
#define HW      262144        // 512*512
#define NTILES  16384         // 2M pixels / 128-pixel tiles
#define GRID1   296           // 2 * 148 SMs
#define K       19
#define KC      1216          // 19*64

// Scratch (no allocation allowed -> __device__ globals)
__device__ float g_psums[GRID1 * KC];
__device__ int   g_pcnts[K * GRID1];     // [class][block] - coalesced for K3 warps

#define TILE_F   8192
// dyn smem: 2 tiles + order[2][128] + bstart/bcnt/bcur[2][19]
#define SMEM_BYTES (2*TILE_F*4 + 2*128*4 + 3*2*19*4 + 64)

// ---------------------------------------------------------------------------
// K1: streaming centroid scatter-sum, class-owned register accumulation,
// double-buffered single-barrier pipeline.
//   Tile layout: [pixel 0..127][col], col = 2*((c&31) ^ (pixel>>2)) + (c>>5)
//   -> channel pair (c, c+32) adjacent (float2 ops), conflict-free both ways.
//   Per iteration (ONE __syncthreads):
//     warps 0..15: STS.64 tile t into buf[par], then LDG.128 prefetch t+G
//     warp 19:     counting-sort labels of tile t into meta[par]; prefetch labels
//     warps 0..18: accumulate tile t-G from buf[par^1]/meta[par^1] into regs
// ---------------------------------------------------------------------------
__global__ __launch_bounds__(640, 2) void k1_kernel(const float* __restrict__ inp,
                                                    const int* __restrict__ tgt32) {
    extern __shared__ float sm[];
    float* tiles  = sm;                        // [2][8192]
    int*   order  = (int*)(sm + 2 * TILE_F);   // [2][128]
    int*   bstart = order + 256;               // [2][19]
    int*   bcnt   = bstart + 38;               // [2][19]
    int*   bcur   = bcnt + 38;                 // [2][19]

    const int tid  = threadIdx.x;
    const int lane = tid & 31;
    const int wid  = tid >> 5;
    const int bid  = blockIdx.x;

    // loader mapping (tid < 512): q = pixel-quad, channel pairs (w,32+w),(16+w,48+w)
    const int q = tid & 31, w = (tid >> 5) & 15;
    const int c0 = w, c1 = 16 + w, c2 = 32 + w, c3 = 48 + w;
    const int slot0 = 2 * (w ^ q);
    const int slot1 = 2 * ((w ^ q) ^ 16);

    float a0 = 0.f, a1 = 0.f, b0 = 0.f, b1 = 0.f;
    int   ccnt = 0;
    float4 v0, v1, v2, v3;
    int   lab0 = 0, lab1 = 0, lab2 = 0, lab3 = 0;
    int   shift = 0;

    int t = bid, par = 0;

    // ---- prologue: prefetch tile bid (data + labels), detect targets dtype ----
    {
        const int b = t >> 11, hw0 = (t & 2047) << 7;
        if (tid < 512) {
            const float* p = inp + ((size_t)b << 24) + hw0 + (q << 2);
            v0 = __ldcs((const float4*)(p + (size_t)c0 * HW));
            v1 = __ldcs((const float4*)(p + (size_t)c1 * HW));
            v2 = __ldcs((const float4*)(p + (size_t)c2 * HW));
            v3 = __ldcs((const float4*)(p + (size_t)c3 * HW));
        }
        if (wid == 19) {
            // int64 labels 0..18 have all-zero high words; int32 ~never does
            if (lane == 0) {
                int all0 = 1;
                #pragma unroll
                for (int i = 0; i < 32; ++i)
                    if (tgt32[2 * i + 1] != 0) all0 = 0;
                shift = all0;
            }
            shift = __shfl_sync(0xffffffffu, shift, 0);
            const int tb = (b << 18) + hw0;
            lab0 = tgt32[(size_t)(tb + lane)       << shift];
            lab1 = tgt32[(size_t)(tb + lane +  32) << shift];
            lab2 = tgt32[(size_t)(tb + lane +  64) << shift];
            lab3 = tgt32[(size_t)(tb + lane +  96) << shift];
        }
    }

    bool first = true;
    while (true) {
        __syncthreads();
        const bool store = (t < NTILES);
        if (store) {
            if (tid < 512) {   // STS.64, conflict-free
                float* r = tiles + par * TILE_F + (q << 8);
                *(float2*)(r +       slot0) = make_float2(v0.x, v2.x);
                *(float2*)(r +  64 + slot0) = make_float2(v0.y, v2.y);
                *(float2*)(r + 128 + slot0) = make_float2(v0.z, v2.z);
                *(float2*)(r + 192 + slot0) = make_float2(v0.w, v2.w);
                *(float2*)(r +       slot1) = make_float2(v1.x, v3.x);
                *(float2*)(r +  64 + slot1) = make_float2(v1.y, v3.y);
                *(float2*)(r + 128 + slot1) = make_float2(v1.z, v3.z);
                *(float2*)(r + 192 + slot1) = make_float2(v1.w, v3.w);
            } else if (wid == 19) {   // counting sort of 128 labels -> meta[par]
                int* bc = bcnt + par * 19;
                int* bs = bstart + par * 19;
                int* bu = bcur + par * 19;
                int* od = order + par * 128;
                int l0 = min(max(lab0, 0), 18), l1 = min(max(lab1, 0), 18);
                int l2 = min(max(lab2, 0), 18), l3 = min(max(lab3, 0), 18);
                if (lane < 19) bc[lane] = 0;
                __syncwarp();
                atomicAdd(&bc[l0], 1); atomicAdd(&bc[l1], 1);
                atomicAdd(&bc[l2], 1); atomicAdd(&bc[l3], 1);
                __syncwarp();
                int c = (lane < 19) ? bc[lane] : 0;
                int x = c;
                #pragma unroll
                for (int off = 1; off < 32; off <<= 1) {
                    int y = __shfl_up_sync(0xffffffffu, x, off);
                    if (lane >= off) x += y;
                }
                if (lane < 19) { bs[lane] = x - c; bu[lane] = x - c; }
                __syncwarp();
                int p0 = atomicAdd(&bu[l0], 1); od[p0] = lane;
                int p1 = atomicAdd(&bu[l1], 1); od[p1] = lane + 32;
                int p2 = atomicAdd(&bu[l2], 1); od[p2] = lane + 64;
                int p3 = atomicAdd(&bu[l3], 1); od[p3] = lane + 96;
            }
        }
        const int nt = t + GRID1;
        if (nt < NTILES) {   // prefetch next tile (latency spans full iteration)
            const int nb = nt >> 11, nh = (nt & 2047) << 7;
            if (tid < 512) {
                const float* p = inp + ((size_t)nb << 24) + nh + (q << 2);
                v0 = __ldcs((const float4*)(p + (size_t)c0 * HW));
                v1 = __ldcs((const float4*)(p + (size_t)c1 * HW));
                v2 = __ldcs((const float4*)(p + (size_t)c2 * HW));
                v3 = __ldcs((const float4*)(p + (size_t)c3 * HW));
            } else if (wid == 19) {
                const int tb = (nb << 18) + nh;
                lab0 = tgt32[(size_t)(tb + lane)       << shift];
                lab1 = tgt32[(size_t)(tb + lane +  32) << shift];
                lab2 = tgt32[(size_t)(tb + lane +  64) << shift];
                lab3 = tgt32[(size_t)(tb + lane +  96) << shift];
            }
        }
        // accumulate previous tile from buf[par^1] (register accumulators)
        if (!first && wid < K) {
            const int pp   = par ^ 1;
            const int base = bstart[pp * 19 + wid];
            const int n    = bcnt[pp * 19 + wid];
            const int* od  = order + pp * 128;
            const float* tb = tiles + pp * TILE_F;
            ccnt += n;
            int i = 0;
            for (; i + 2 <= n; i += 2) {   // two independent chains
                const int pA = od[base + i], pB = od[base + i + 1];
                float2 fA = *(const float2*)(tb + (pA << 6) + 2 * (lane ^ ((pA >> 2) & 31)));
                float2 fB = *(const float2*)(tb + (pB << 6) + 2 * (lane ^ ((pB >> 2) & 31)));
                a0 += fA.x; a1 += fA.y;
                b0 += fB.x; b1 += fB.y;
            }
            if (i < n) {
                const int pA = od[base + i];
                float2 fA = *(const float2*)(tb + (pA << 6) + 2 * (lane ^ ((pA >> 2) & 31)));
                a0 += fA.x; a1 += fA.y;
            }
        }
        first = false;
        if (!store) break;     // post-last iteration: final accumulate done
        t = nt; par ^= 1;
    }

    // ---- write per-block partials ----
    if (wid < K) {
        g_psums[bid * KC + (wid << 6) + lane]      = a0 + b0;
        g_psums[bid * KC + (wid << 6) + 32 + lane] = a1 + b1;
        if (lane == 0) g_pcnts[wid * GRID1 + bid] = ccnt;
    }
}

// ---------------------------------------------------------------------------
// K3 (fused tail): psums reduce (608 thr, float4, L2-resident) + counts reduce
// (19 warps, shfl) + centroids + cosine-embedding loss. 1 block, 640 threads.
// ---------------------------------------------------------------------------
__global__ __launch_bounds__(640) void k3_kernel(float* __restrict__ out) {
    __shared__ float4 part[608];
    __shared__ float  cen[KC];
    __shared__ float  nrm[K];
    __shared__ int    cnts[K];
    __shared__ float  red[512];
    const int tid = threadIdx.x;
    const int wid = tid >> 5, lane = tid & 31;

    // counts: warp per class, coalesced row + shfl tree
    if (wid < K) {
        int s = 0;
        #pragma unroll
        for (int p = lane; p < GRID1; p += 32) s += g_pcnts[wid * GRID1 + p];
        #pragma unroll
        for (int off = 16; off > 0; off >>= 1) s += __shfl_xor_sync(0xffffffffu, s, off);
        if (lane == 0) cnts[wid] = s;
    }
    // psums reduce: col = tid%304 (float4 of 4 outputs), half rows each
    if (tid < 608) {
        const int col = tid % 304, half = tid / 304;
        const float4* ps = (const float4*)g_psums;
        float4 s = make_float4(0.f, 0.f, 0.f, 0.f);
        const int r1 = half * 148 + 148;
        for (int r = half * 148; r < r1; ++r) {
            float4 v = ps[r * 304 + col];
            s.x += v.x; s.y += v.y; s.z += v.z; s.w += v.w;
        }
        part[tid] = s;
    }
    __syncthreads();
    if (tid < 304) {
        float4 aa = part[tid], bb = part[tid + 304];
        ((float4*)cen)[tid] = make_float4(aa.x + bb.x, aa.y + bb.y, aa.z + bb.z, aa.w + bb.w);
    }
    __syncthreads();
    for (int i = tid; i < KC; i += 640)
        cen[i] = cen[i] / fmaxf((float)cnts[i >> 6], 1.0f);
    __syncthreads();
    if (tid < K) {
        float nn = 0.f;
        #pragma unroll
        for (int c = 0; c < 64; ++c) { float v = cen[(tid << 6) + c]; nn += v * v; }
        nrm[tid] = fmaxf(sqrtf(nn), 1e-8f);
    }
    __syncthreads();
    for (int i = tid; i < KC; i += 640)
        cen[i] = cen[i] / nrm[i >> 6];
    __syncthreads();

    float val = 0.f;
    if (tid < K * K) {
        const int k1i = tid / K, k2i = tid % K;
        float dot = 0.f;
        #pragma unroll
        for (int c = 0; c < 64; ++c)
            dot += cen[(k1i << 6) + c] * cen[(k2i << 6) + c];
        val = (k1i == k2i) ? (1.0f - dot) : fmaxf(dot, 0.0f);
    }
    if (tid < 512) red[tid] = val;
    __syncthreads();
    #pragma unroll
    for (int off = 256; off > 0; off >>= 1) {
        if (tid < off) red[tid] += red[tid + off];
        __syncthreads();
    }
    if (tid == 0) out[0] = red[0] / 6859.0f;   // K^3
}

// ---------------------------------------------------------------------------
extern "C" void kernel_launch(void* const* d_in, const int* in_sizes, int n_in,
                              void* d_out, int out_size) {
    // Select pointers by element count (inputs: 134M, targets: 2M) — robust to order.
    int ii = 0, ti = 1;
    if (n_in >= 2 && in_sizes[1] > in_sizes[0]) { ii = 1; ti = 0; }
    const float* inp = (const float*)d_in[ii];
    const int* tgt32 = (const int*)d_in[ti];
    cudaFuncSetAttribute(k1_kernel, cudaFuncAttributeMaxDynamicSharedMemorySize, SMEM_BYTES);
    k1_kernel<<<GRID1, 640, SMEM_BYTES>>>(inp, tgt32);
    k3_kernel<<<1, 640>>>((float*)d_out);
}

// round 6
// speedup vs baseline: 1.7407x; 1.0685x over previous
#include <cuda_runtime.h>
#include <math.h>

// Problem constants
#define HW      262144        // 512*512
#define NTILES  16384         // 2M pixels / 128-pixel tiles
#define GRID1   296           // 2 * 148 SMs
#define K       19
#define KC      1216          // 19*64

// Scratch (no allocation allowed -> __device__ globals)
__device__ float g_psums[GRID1 * KC];
__device__ int   g_pcnts[K * GRID1];     // [class][block] - coalesced for K3 warps
__device__ float g_sums[KC];

#define TILE_F   8192
// dyn smem: 2 tiles + order[2][128] + bstart/bcnt/bcur[2][19]
#define SMEM_BYTES (2*TILE_F*4 + 2*128*4 + 3*2*19*4 + 64)

// ---------------------------------------------------------------------------
// K1: streaming centroid scatter-sum, class-owned register accumulation,
// double-buffered single-barrier pipeline. (unchanged from R5 — measured ~73us)
// ---------------------------------------------------------------------------
__global__ __launch_bounds__(640, 2) void k1_kernel(const float* __restrict__ inp,
                                                    const int* __restrict__ tgt32) {
    extern __shared__ float sm[];
    float* tiles  = sm;                        // [2][8192]
    int*   order  = (int*)(sm + 2 * TILE_F);   // [2][128]
    int*   bstart = order + 256;               // [2][19]
    int*   bcnt   = bstart + 38;               // [2][19]
    int*   bcur   = bcnt + 38;                 // [2][19]

    const int tid  = threadIdx.x;
    const int lane = tid & 31;
    const int wid  = tid >> 5;
    const int bid  = blockIdx.x;

    // loader mapping (tid < 512): q = pixel-quad, channel pairs (w,32+w),(16+w,48+w)
    const int q = tid & 31, w = (tid >> 5) & 15;
    const int c0 = w, c1 = 16 + w, c2 = 32 + w, c3 = 48 + w;
    const int slot0 = 2 * (w ^ q);
    const int slot1 = 2 * ((w ^ q) ^ 16);

    float a0 = 0.f, a1 = 0.f, b0 = 0.f, b1 = 0.f;
    int   ccnt = 0;
    float4 v0, v1, v2, v3;
    int   lab0 = 0, lab1 = 0, lab2 = 0, lab3 = 0;
    int   shift = 0;

    int t = bid, par = 0;

    // ---- prologue: prefetch tile bid (data + labels), detect targets dtype ----
    {
        const int b = t >> 11, hw0 = (t & 2047) << 7;
        if (tid < 512) {
            const float* p = inp + ((size_t)b << 24) + hw0 + (q << 2);
            v0 = __ldcs((const float4*)(p + (size_t)c0 * HW));
            v1 = __ldcs((const float4*)(p + (size_t)c1 * HW));
            v2 = __ldcs((const float4*)(p + (size_t)c2 * HW));
            v3 = __ldcs((const float4*)(p + (size_t)c3 * HW));
        }
        if (wid == 19) {
            // int64 labels 0..18 have all-zero high words; int32 ~never does
            if (lane == 0) {
                int all0 = 1;
                #pragma unroll
                for (int i = 0; i < 32; ++i)
                    if (tgt32[2 * i + 1] != 0) all0 = 0;
                shift = all0;
            }
            shift = __shfl_sync(0xffffffffu, shift, 0);
            const int tb = (b << 18) + hw0;
            lab0 = tgt32[(size_t)(tb + lane)       << shift];
            lab1 = tgt32[(size_t)(tb + lane +  32) << shift];
            lab2 = tgt32[(size_t)(tb + lane +  64) << shift];
            lab3 = tgt32[(size_t)(tb + lane +  96) << shift];
        }
    }

    bool first = true;
    while (true) {
        __syncthreads();
        const bool store = (t < NTILES);
        if (store) {
            if (tid < 512) {   // STS.64, conflict-free
                float* r = tiles + par * TILE_F + (q << 8);
                *(float2*)(r +       slot0) = make_float2(v0.x, v2.x);
                *(float2*)(r +  64 + slot0) = make_float2(v0.y, v2.y);
                *(float2*)(r + 128 + slot0) = make_float2(v0.z, v2.z);
                *(float2*)(r + 192 + slot0) = make_float2(v0.w, v2.w);
                *(float2*)(r +       slot1) = make_float2(v1.x, v3.x);
                *(float2*)(r +  64 + slot1) = make_float2(v1.y, v3.y);
                *(float2*)(r + 128 + slot1) = make_float2(v1.z, v3.z);
                *(float2*)(r + 192 + slot1) = make_float2(v1.w, v3.w);
            } else if (wid == 19) {   // counting sort of 128 labels -> meta[par]
                int* bc = bcnt + par * 19;
                int* bs = bstart + par * 19;
                int* bu = bcur + par * 19;
                int* od = order + par * 128;
                int l0 = min(max(lab0, 0), 18), l1 = min(max(lab1, 0), 18);
                int l2 = min(max(lab2, 0), 18), l3 = min(max(lab3, 0), 18);
                if (lane < 19) bc[lane] = 0;
                __syncwarp();
                atomicAdd(&bc[l0], 1); atomicAdd(&bc[l1], 1);
                atomicAdd(&bc[l2], 1); atomicAdd(&bc[l3], 1);
                __syncwarp();
                int c = (lane < 19) ? bc[lane] : 0;
                int x = c;
                #pragma unroll
                for (int off = 1; off < 32; off <<= 1) {
                    int y = __shfl_up_sync(0xffffffffu, x, off);
                    if (lane >= off) x += y;
                }
                if (lane < 19) { bs[lane] = x - c; bu[lane] = x - c; }
                __syncwarp();
                int p0 = atomicAdd(&bu[l0], 1); od[p0] = lane;
                int p1 = atomicAdd(&bu[l1], 1); od[p1] = lane + 32;
                int p2 = atomicAdd(&bu[l2], 1); od[p2] = lane + 64;
                int p3 = atomicAdd(&bu[l3], 1); od[p3] = lane + 96;
            }
        }
        const int nt = t + GRID1;
        if (nt < NTILES) {   // prefetch next tile (latency spans full iteration)
            const int nb = nt >> 11, nh = (nt & 2047) << 7;
            if (tid < 512) {
                const float* p = inp + ((size_t)nb << 24) + nh + (q << 2);
                v0 = __ldcs((const float4*)(p + (size_t)c0 * HW));
                v1 = __ldcs((const float4*)(p + (size_t)c1 * HW));
                v2 = __ldcs((const float4*)(p + (size_t)c2 * HW));
                v3 = __ldcs((const float4*)(p + (size_t)c3 * HW));
            } else if (wid == 19) {
                const int tb = (nb << 18) + nh;
                lab0 = tgt32[(size_t)(tb + lane)       << shift];
                lab1 = tgt32[(size_t)(tb + lane +  32) << shift];
                lab2 = tgt32[(size_t)(tb + lane +  64) << shift];
                lab3 = tgt32[(size_t)(tb + lane +  96) << shift];
            }
        }
        // accumulate previous tile from buf[par^1] (register accumulators)
        if (!first && wid < K) {
            const int pp   = par ^ 1;
            const int base = bstart[pp * 19 + wid];
            const int n    = bcnt[pp * 19 + wid];
            const int* od  = order + pp * 128;
            const float* tb = tiles + pp * TILE_F;
            ccnt += n;
            int i = 0;
            for (; i + 2 <= n; i += 2) {   // two independent chains
                const int pA = od[base + i], pB = od[base + i + 1];
                float2 fA = *(const float2*)(tb + (pA << 6) + 2 * (lane ^ ((pA >> 2) & 31)));
                float2 fB = *(const float2*)(tb + (pB << 6) + 2 * (lane ^ ((pB >> 2) & 31)));
                a0 += fA.x; a1 += fA.y;
                b0 += fB.x; b1 += fB.y;
            }
            if (i < n) {
                const int pA = od[base + i];
                float2 fA = *(const float2*)(tb + (pA << 6) + 2 * (lane ^ ((pA >> 2) & 31)));
                a0 += fA.x; a1 += fA.y;
            }
        }
        first = false;
        if (!store) break;     // post-last iteration: final accumulate done
        t = nt; par ^= 1;
    }

    // ---- write per-block partials ----
    if (wid < K) {
        g_psums[bid * KC + (wid << 6) + lane]      = a0 + b0;
        g_psums[bid * KC + (wid << 6) + 32 + lane] = a1 + b1;
        if (lane == 0) g_pcnts[wid * GRID1 + bid] = ccnt;
    }
}

// ---------------------------------------------------------------------------
// K2: wide psums reduce. 152 blocks x 256 threads; block owns 2 float4-columns
// (304 total); 128 threads/column read rows stride-128 (coalesced) + smem tree.
// ---------------------------------------------------------------------------
__global__ __launch_bounds__(256) void k2_kernel() {
    __shared__ float4 red[256];
    const int tid = threadIdx.x;
    const int half = tid >> 7;                 // which of the 2 columns
    const int r    = tid & 127;                // row lane within column
    const int col  = (blockIdx.x << 1) + half; // 0..303
    const float4* ps = (const float4*)g_psums;
    float4 s = make_float4(0.f, 0.f, 0.f, 0.f);
    for (int row = r; row < GRID1; row += 128) {
        float4 v = ps[row * 304 + col];
        s.x += v.x; s.y += v.y; s.z += v.z; s.w += v.w;
    }
    red[tid] = s;
    __syncthreads();
    #pragma unroll
    for (int off = 64; off > 0; off >>= 1) {
        if (r < off) {
            float4 o = red[tid + off];
            s.x += o.x; s.y += o.y; s.z += o.z; s.w += o.w;
            red[tid] = s;
        }
        __syncthreads();
    }
    if (r == 0) ((float4*)g_sums)[col] = red[half << 7];
}

// ---------------------------------------------------------------------------
// K3: counts reduce (19 warps, coalesced + shfl) + centroids + loss. 1 block.
// ---------------------------------------------------------------------------
__global__ __launch_bounds__(640) void k3_kernel(float* __restrict__ out) {
    __shared__ float cen[KC];
    __shared__ float nrm[K];
    __shared__ int   cnts[K];
    __shared__ float red[512];
    const int tid = threadIdx.x;
    const int wid = tid >> 5, lane = tid & 31;

    if (wid < K) {
        int s = 0;
        #pragma unroll
        for (int p = lane; p < GRID1; p += 32) s += g_pcnts[wid * GRID1 + p];
        #pragma unroll
        for (int off = 16; off > 0; off >>= 1) s += __shfl_xor_sync(0xffffffffu, s, off);
        if (lane == 0) cnts[wid] = s;
    }
    __syncthreads();
    for (int i = tid; i < KC; i += 640)
        cen[i] = g_sums[i] / fmaxf((float)cnts[i >> 6], 1.0f);
    __syncthreads();
    if (tid < K) {
        float nn = 0.f;
        #pragma unroll
        for (int c = 0; c < 64; ++c) { float v = cen[(tid << 6) + c]; nn += v * v; }
        nrm[tid] = fmaxf(sqrtf(nn), 1e-8f);
    }
    __syncthreads();
    for (int i = tid; i < KC; i += 640)
        cen[i] = cen[i] / nrm[i >> 6];
    __syncthreads();

    float val = 0.f;
    if (tid < K * K) {
        const int k1i = tid / K, k2i = tid % K;
        float dot = 0.f;
        #pragma unroll
        for (int c = 0; c < 64; ++c)
            dot += cen[(k1i << 6) + c] * cen[(k2i << 6) + c];
        val = (k1i == k2i) ? (1.0f - dot) : fmaxf(dot, 0.0f);
    }
    if (tid < 512) red[tid] = val;
    __syncthreads();
    #pragma unroll
    for (int off = 256; off > 0; off >>= 1) {
        if (tid < off) red[tid] += red[tid + off];
        __syncthreads();
    }
    if (tid == 0) out[0] = red[0] / 6859.0f;   // K^3
}

// ---------------------------------------------------------------------------
extern "C" void kernel_launch(void* const* d_in, const int* in_sizes, int n_in,
                              void* d_out, int out_size) {
    // Select pointers by element count (inputs: 134M, targets: 2M) — robust to order.
    int ii = 0, ti = 1;
    if (n_in >= 2 && in_sizes[1] > in_sizes[0]) { ii = 1; ti = 0; }
    const float* inp = (const float*)d_in[ii];
    const int* tgt32 = (const int*)d_in[ti];
    cudaFuncSetAttribute(k1_kernel, cudaFuncAttributeMaxDynamicSharedMemorySize, SMEM_BYTES);
    k1_kernel<<<GRID1, 640, SMEM_BYTES>>>(inp, tgt32);
    k2_kernel<<<152, 256>>>();
    k3_kernel<<<1, 640>>>((float*)d_out);
}